// round 16
// baseline (speedup 1.0000x reference)
#include <cuda_runtime.h>
#include <math.h>
#include <stdint.h>

#define C 64
#define P (512 * 512)
#define K 20
#define NUM_CLASSES 11
#define EPS 1e-8f

#define GRID 296                 // 2 CTAs x 148 SMs
#define TK 64                    // pixels per MMA tile
#define TOTAL_TILES (P / TK)     // 4096
#define BASE_TILES (TOTAL_TILES / GRID)          // 13
#define EXTRA (TOTAL_TILES - GRID * BASE_TILES)  // 248 blocks get 14

#define ASTRIDE 68               // padded row stride: MMA-frag LDS conflict-free
#define A_FLOATS (128 * ASTRIDE)
#define RED_FLOATS 2048          // aliased: s_red1|s_red2 (2048) / s_bf (24*68=1632)
#define DYN_FLOATS (A_FLOATS + RED_FLOATS)
#define DYN_SZ (DYN_FLOATS * 4)  // 43008 B < 48K default limit

// reduced sums: sum1[20][64] | usum[20][64] | cnt[20] | sq[20]
#define PART_STRIDE 2600
#define OFF_SUM1 0
#define OFF_USUM 1280
#define OFF_CNT 2560
#define OFF_SQ 2580

static __device__ float g_red[PART_STRIDE];   // zero-init; finalize tail re-zeroes
static __device__ unsigned int g_ticket;      // zero-init; finalize tail resets

// tf32 m16n8k8 row.col MMA (sm_80+, works at compute_100)
__device__ __forceinline__ void mma_tf32(float& d0, float& d1, float& d2, float& d3,
                                         uint32_t a0, uint32_t a1, uint32_t a2, uint32_t a3,
                                         uint32_t b0, uint32_t b1)
{
    asm volatile(
        "mma.sync.aligned.m16n8k8.row.col.f32.tf32.tf32.f32 "
        "{%0,%1,%2,%3}, {%4,%5,%6,%7}, {%8,%9}, {%0,%1,%2,%3};"
        : "+f"(d0), "+f"(d1), "+f"(d2), "+f"(d3)
        : "r"(a0), "r"(a1), "r"(a2), "r"(a3), "r"(b0), "r"(b1));
}

__device__ __forceinline__ void hi_lo(float v, uint32_t& h, uint32_t& l)
{
    uint32_t hu = __float_as_uint(v) & 0xFFFFE000u;   // tf32 truncation
    h = hu;
    l = __float_as_uint(v - __uint_as_float(hu));     // residual
}

// ---------------------------------------------------------------------------
// Single fused kernel.
// Main loop: warp-tiled tf32 MMA, software-pipelined. CONTIGUOUS uneven tile
// assignment: blocks 0..EXTRA-1 own 14 consecutive tiles starting at b*14;
// the rest own 13 starting at EXTRA*14 + (b-EXTRA)*13. Streaming locality of
// the contiguous layout + balanced 28-unit critical wave.
// Epilogue atomics into g_red; threadfence-ticket: last block finalizes in
// the dead dynamic smem region.
// ---------------------------------------------------------------------------
__global__ void __launch_bounds__(256, 2)
fused_kernel(const float* __restrict__ v1g,
             const float* __restrict__ v2g,
             const int* __restrict__ masks,
             const int* __restrict__ labels,
             float* __restrict__ out)
{
    extern __shared__ float dyn[];
    float* s_a    = dyn;                       // [128][68]
    float* s_red1 = dyn + A_FLOATS;            // [1024]   (Phase A-B)
    float* s_red2 = dyn + A_FLOATS + 1024;     // [1024]   (Phase A-B)
    float* s_bf   = dyn + A_FLOATS;            // [24][68] (Phase C-D, aliases s_red)

    __shared__ float s_s1[64];
    __shared__ float s_inv[64];
    __shared__ unsigned int isLast;

    const int tid = threadIdx.x;
    const int wid = tid >> 5;
    const int lane = tid & 31;
    const int g  = lane >> 2;
    const int tg = lane & 3;
    const int f4 = tid & 15;
    const int cr = tid >> 4;

    int mk[5], mp[5];
#pragma unroll
    for (int r = 0; r < 5; ++r) {
        int e = tid + 256 * r;
        mk[r] = e >> 6;
        mp[r] = e & 63;
    }

    float acc[3][4];
#pragma unroll
    for (int nt = 0; nt < 3; ++nt)
#pragma unroll
        for (int q = 0; q < 4; ++q) acc[nt][q] = 0.f;

    float cntAcc = 0.f, sqAcc = 0.f;
    const int b = blockIdx.x;
    const int nTiles = BASE_TILES + (b < EXTRA ? 1 : 0);
    const int tile0  = (b < EXTRA) ? b * (BASE_TILES + 1)
                                   : EXTRA * (BASE_TILES + 1) + (b - EXTRA) * BASE_TILES;
    const int rowA0 = 16 * wid + g;
    size_t p0 = (size_t)tile0 * TK;            // contiguous tiles: stride TK

    // ---- prologue: load tile 0 -------------------------------------------
    float4 av[4], bv[4];
    int mreg[5];
#pragma unroll
    for (int i = 0; i < 4; ++i) {
        int c = cr + 16 * i;
        av[i] = *(const float4*)(v1g + (size_t)c * P + p0 + 4 * f4);
        bv[i] = *(const float4*)(v2g + (size_t)c * P + p0 + 4 * f4);
    }
#pragma unroll
    for (int r = 0; r < 5; ++r)
        mreg[r] = masks[(size_t)mk[r] * P + p0 + mp[r]];

    for (int t = 0; t < nTiles; ++t) {
        const size_t p1 = p0 + TK;             // next contiguous tile
        __syncthreads();

        // Phase A
        float4 pp1 = make_float4(0.f, 0.f, 0.f, 0.f);
        float4 pp2 = make_float4(0.f, 0.f, 0.f, 0.f);
#pragma unroll
        for (int i = 0; i < 4; ++i) {
            int c = cr + 16 * i;
            float4 a = av[i];
            pp1.x = fmaf(a.x, a.x, pp1.x); pp1.y = fmaf(a.y, a.y, pp1.y);
            pp1.z = fmaf(a.z, a.z, pp1.z); pp1.w = fmaf(a.w, a.w, pp1.w);
            *(float4*)&s_a[c * ASTRIDE + 4 * f4] = a;
            float4 bb = bv[i];
            pp2.x = fmaf(bb.x, bb.x, pp2.x); pp2.y = fmaf(bb.y, bb.y, pp2.y);
            pp2.z = fmaf(bb.z, bb.z, pp2.z); pp2.w = fmaf(bb.w, bb.w, pp2.w);
            *(float4*)&s_a[(64 + c) * ASTRIDE + 4 * f4] = bb;
        }
        *(float4*)&s_red1[tid * 4] = pp1;
        *(float4*)&s_red2[tid * 4] = pp2;

        if (t + 1 < nTiles) {
#pragma unroll
            for (int i = 0; i < 4; ++i) {
                int c = cr + 16 * i;
                av[i] = *(const float4*)(v1g + (size_t)c * P + p1 + 4 * f4);
                bv[i] = *(const float4*)(v2g + (size_t)c * P + p1 + 4 * f4);
            }
        }
        __syncthreads();

        // Phase B
        if (tid < TK) {
            int q = tid >> 2, cm = tid & 3;
            float s1 = 0.f, s2 = 0.f;
#pragma unroll
            for (int r = 0; r < 16; ++r) {
                s1 += s_red1[(r * 16 + q) * 4 + cm];
                s2 += s_red2[(r * 16 + q) * 4 + cm];
            }
            s_s1[tid]  = s1;
            s_inv[tid] = 1.0f / fmaxf(sqrtf(s2), EPS);
        }
        __syncthreads();

        // Phase C
        {
            float4 iv = *(const float4*)&s_inv[4 * f4];
#pragma unroll
            for (int i = 0; i < 4; ++i) {
                int c = cr + 16 * i;
                float4 bb = *(const float4*)&s_a[(64 + c) * ASTRIDE + 4 * f4];
                bb.x *= iv.x; bb.y *= iv.y; bb.z *= iv.z; bb.w *= iv.w;
                *(float4*)&s_a[(64 + c) * ASTRIDE + 4 * f4] = bb;
            }
        }
#pragma unroll
        for (int r = 0; r < 5; ++r)
            s_bf[mk[r] * ASTRIDE + mp[r]] = (float)(mreg[r] & 1);
        s_bf[(20 + (tid >> 6)) * ASTRIDE + (tid & 63)] = 0.f;

        if (t + 1 < nTiles) {
#pragma unroll
            for (int r = 0; r < 5; ++r)
                mreg[r] = masks[(size_t)mk[r] * P + p1 + mp[r]];
        }
        __syncthreads();

        // Phase D
#pragma unroll
        for (int s = 0; s < 8; ++s) {
            int c0 = 8 * s + tg;
            int c1 = c0 + 4;
            float ra0 = s_a[rowA0 * ASTRIDE + c0];
            float ra1 = s_a[(rowA0 + 8) * ASTRIDE + c0];
            float ra2 = s_a[rowA0 * ASTRIDE + c1];
            float ra3 = s_a[(rowA0 + 8) * ASTRIDE + c1];
            uint32_t h0, l0, h1, l1, h2, l2, h3, l3;
            hi_lo(ra0, h0, l0); hi_lo(ra1, h1, l1);
            hi_lo(ra2, h2, l2); hi_lo(ra3, h3, l3);
#pragma unroll
            for (int nt = 0; nt < 3; ++nt) {
                int n0 = 8 * nt + g;
                uint32_t b0 = __float_as_uint(s_bf[n0 * ASTRIDE + c0]);
                uint32_t b1 = __float_as_uint(s_bf[n0 * ASTRIDE + c1]);
                mma_tf32(acc[nt][0], acc[nt][1], acc[nt][2], acc[nt][3],
                         h0, h1, h2, h3, b0, b1);
                mma_tf32(acc[nt][0], acc[nt][1], acc[nt][2], acc[nt][3],
                         l0, l1, l2, l3, b0, b1);
            }
        }
        if (tid < K) {
            float c0 = 0.f, s0 = 0.f;
#pragma unroll 8
            for (int p = 0; p < TK; ++p) {
                float m = s_bf[tid * ASTRIDE + p];
                c0 += m;
                s0 = fmaf(m, s_s1[p], s0);
            }
            cntAcc += c0;
            sqAcc  += s0;
        }
        p0 = p1;
    }

    // ---- epilogue: atomics into g_red -------------------------------------
    {
        int m0 = rowA0;
        int m1 = rowA0 + 8;
        int off0 = (m0 < 64) ? (OFF_SUM1 + m0) : (OFF_USUM + (m0 - 64));
        int off1 = (m1 < 64) ? (OFF_SUM1 + m1) : (OFF_USUM + (m1 - 64));
#pragma unroll
        for (int nt = 0; nt < 3; ++nt) {
            int n0 = 8 * nt + 2 * tg;
            if (n0 < K) {
                atomicAdd(&g_red[off0 + n0 * C], acc[nt][0]);
                atomicAdd(&g_red[off1 + n0 * C], acc[nt][2]);
            }
            if (n0 + 1 < K) {
                atomicAdd(&g_red[off0 + (n0 + 1) * C], acc[nt][1]);
                atomicAdd(&g_red[off1 + (n0 + 1) * C], acc[nt][3]);
            }
        }
    }
    if (tid < K) {
        atomicAdd(&g_red[OFF_CNT + tid], cntAcc);
        atomicAdd(&g_red[OFF_SQ  + tid], sqAcc);
    }

    // ---- ticket: last block finalizes -------------------------------------
    __syncthreads();
    if (tid == 0) {
        __threadfence();
        unsigned int tk = atomicAdd(&g_ticket, 1u);
        isLast = (tk == (unsigned int)(GRID - 1)) ? 1u : 0u;
    }
    __syncthreads();
    if (!isLast) return;
    __threadfence();

    // ---- finalize (256 threads; scratch in dead dynamic smem) -------------
    float* S    = dyn;             // [2600]
    float* m1n  = dyn + 2600;      // [K*C]
    float* simm = dyn + 3880;      // [K*K]
    __shared__ float stdv[K];
    __shared__ int   s_cls[K];

    for (int i = tid; i < PART_STRIDE; i += 256) S[i] = g_red[i];
    if (tid < K) s_cls[tid] = labels[tid];
    __syncthreads();

    // reset globals for next graph replay (S holds the values now)
    for (int i = tid; i < PART_STRIDE; i += 256) g_red[i] = 0.f;
    if (tid == 0) g_ticket = 0u;

    // per-instance stats: warp per k, 3 rounds
    for (int k = wid; k < K; k += 8) {
        float cnt = S[OFF_CNT + k];
        float rc  = 1.0f / cnt;
        float v0 = S[OFF_SUM1 + k * C + lane];
        float v1 = S[OFF_SUM1 + k * C + lane + 32];
        float ssum = v0 + v1;
        float m0 = v0 * rc, m1 = v1 * rc;
        float nrm2 = fmaf(m0, m0, m1 * m1);
#pragma unroll
        for (int off = 16; off > 0; off >>= 1) {
            ssum += __shfl_xor_sync(0xFFFFFFFFu, ssum, off);
            nrm2 += __shfl_xor_sync(0xFFFFFFFFu, nrm2, off);
        }
        float n_elem = cnt * (float)C;
        float em  = ssum / n_elem;
        if (lane == 0) {
            float var = (S[OFF_SQ + k] - n_elem * em * em) / (n_elem - 1.0f);
            stdv[k] = sqrtf(fmaxf(var, 0.0f));
        }
        float inv = 1.0f / fmaxf(sqrtf(nrm2), EPS);
        m1n[k * C + lane]      = m0 * inv;
        m1n[k * C + lane + 32] = m1 * inv;
        S[OFF_USUM + k * C + lane]      *= rc;
        S[OFF_USUM + k * C + lane + 32] *= rc;
    }
    __syncthreads();

    // sim dots: 400 over 256 threads, 4-way split accumulators
    for (int e = tid; e < K * K; e += 256) {
        int ki = e / K;
        int kj = e - ki * K;
        const float* a = &m1n[ki * C];
        const float* bb = &S[OFF_USUM + kj * C];
        float d0 = 0.f, d1 = 0.f, d2 = 0.f, d3 = 0.f;
#pragma unroll
        for (int cc = 0; cc < C; cc += 4) {
            d0 = fmaf(a[cc],     bb[cc],     d0);
            d1 = fmaf(a[cc + 1], bb[cc + 1], d1);
            d2 = fmaf(a[cc + 2], bb[cc + 2], d2);
            d3 = fmaf(a[cc + 3], bb[cc + 3], d3);
        }
        simm[e] = (d0 + d1) + (d2 + d3);
    }
    __syncthreads();

    if (wid == 0) {
        float ns = 0.f, nc = 0.f;
        for (int e = lane; e < K * K; e += 32) {
            int ki = e / K, kj = e - ki * K;
            if (s_cls[ki] != s_cls[kj]) { ns += simm[e]; nc += 1.0f; }
        }
#pragma unroll
        for (int off = 16; off > 0; off >>= 1) {
            ns += __shfl_xor_sync(0xFFFFFFFFu, ns, off);
            nc += __shfl_xor_sync(0xFFFFFFFFu, nc, off);
        }
        if (lane == 0) out[22] = ns / nc;
    } else {
        // warps 1-7: classes cl = wid-1, wid+6
        for (int cl = wid - 1; cl < NUM_CLASSES; cl += 7) {
            float inst = 0.f, st = 0.f, cs = 0.f, cnt = 0.f;
            if (lane < K && s_cls[lane] == cl) {
                const int ki = lane;
                inst = simm[ki * K + ki];
                st   = stdv[ki];
                cnt  = 1.0f;
#pragma unroll
                for (int kj = 0; kj < K; ++kj)
                    if (kj != ki && s_cls[kj] == cl) cs += simm[ki * K + kj];
            }
#pragma unroll
            for (int off = 16; off > 0; off >>= 1) {
                inst += __shfl_xor_sync(0xFFFFFFFFu, inst, off);
                st   += __shfl_xor_sync(0xFFFFFFFFu, st,   off);
                cs   += __shfl_xor_sync(0xFFFFFFFFu, cs,   off);
                cnt  += __shfl_xor_sync(0xFFFFFFFFu, cnt,  off);
            }
            if (lane == 0) {
                if (cnt > 1.0f) {
                    inst /= cnt;
                    cs   /= cnt * (cnt - 1.0f);
                    st   /= cnt;
                }
                out[cl]      = inst;
                out[11 + cl] = cs;
                out[23 + cl] = st;
            }
        }
    }
}

extern "C" void kernel_launch(void* const* d_in, const int* in_sizes, int n_in,
                              void* d_out, int out_size)
{
    const float* v1     = (const float*)d_in[0];
    const float* v2     = (const float*)d_in[1];
    const int*   labels = (const int*)d_in[2];
    const int*   masks  = (const int*)d_in[3];
    float* out = (float*)d_out;

    fused_kernel<<<GRID, 256, DYN_SZ>>>(v1, v2, masks, labels, out);
}

// round 17
// speedup vs baseline: 1.1673x; 1.1673x over previous
#include <cuda_runtime.h>
#include <math.h>
#include <stdint.h>

#define C 64
#define P (512 * 512)
#define K 20
#define NUM_CLASSES 11
#define EPS 1e-8f

#define GRID 296                 // 2 CTAs x 148 SMs
#define TK 64                    // pixels per MMA tile
#define TOTAL_TILES (P / TK)     // 4096
#define BASE_TILES (TOTAL_TILES / GRID)          // 13
#define EXTRA (TOTAL_TILES - GRID * BASE_TILES)  // 248 blocks get 14

#define ASTRIDE 68               // padded row stride: MMA-frag LDS conflict-free
#define A_FLOATS (128 * ASTRIDE)
#define RED_FLOATS 2048          // aliased: s_red1|s_red2 (2048) / s_bf (24*68=1632)
#define DYN_FLOATS (A_FLOATS + RED_FLOATS)
#define DYN_SZ (DYN_FLOATS * 4)  // 43008 B < 48K default limit

// reduced sums: sum1[20][64] | usum[20][64] | cnt[20] | sq[20]
#define PART_STRIDE 2600
#define OFF_SUM1 0
#define OFF_USUM 1280
#define OFF_CNT 2560
#define OFF_SQ 2580

static __device__ float g_red[PART_STRIDE];   // zero-init; finalize tail re-zeroes
static __device__ unsigned int g_ticket;      // zero-init; finalize tail resets

// tf32 m16n8k8 row.col MMA (sm_80+, works at compute_100)
__device__ __forceinline__ void mma_tf32(float& d0, float& d1, float& d2, float& d3,
                                         uint32_t a0, uint32_t a1, uint32_t a2, uint32_t a3,
                                         uint32_t b0, uint32_t b1)
{
    asm volatile(
        "mma.sync.aligned.m16n8k8.row.col.f32.tf32.tf32.f32 "
        "{%0,%1,%2,%3}, {%4,%5,%6,%7}, {%8,%9}, {%0,%1,%2,%3};"
        : "+f"(d0), "+f"(d1), "+f"(d2), "+f"(d3)
        : "r"(a0), "r"(a1), "r"(a2), "r"(a3), "r"(b0), "r"(b1));
}

// round-to-nearest tf32 conversion (unbiased, single instruction)
__device__ __forceinline__ uint32_t to_tf32(float v)
{
    uint32_t r;
    asm("cvt.rna.tf32.f32 %0, %1;" : "=r"(r) : "f"(v));
    return r;
}

// ---------------------------------------------------------------------------
// Single fused kernel.
// Main loop: warp-tiled tf32 MMA (hi-only, rna rounding), software-pipelined,
// contiguous uneven tile assignment. v2 normalized straight from registers in
// Phase C (no raw smem round trip). cnt/sq spread over 160 threads.
// Epilogue atomics into g_red; threadfence-ticket: last block finalizes in
// the dead dynamic smem region.
// ---------------------------------------------------------------------------
__global__ void __launch_bounds__(256, 2)
fused_kernel(const float* __restrict__ v1g,
             const float* __restrict__ v2g,
             const int* __restrict__ masks,
             const int* __restrict__ labels,
             float* __restrict__ out)
{
    extern __shared__ float dyn[];
    float* s_a    = dyn;                       // [128][68]
    float* s_red1 = dyn + A_FLOATS;            // [1024]   (Phase A-B)
    float* s_red2 = dyn + A_FLOATS + 1024;     // [1024]   (Phase A-B)
    float* s_bf   = dyn + A_FLOATS;            // [24][68] (Phase C-D, aliases s_red)

    __shared__ float s_s1[64];
    __shared__ float s_inv[64];
    __shared__ unsigned int isLast;

    const int tid = threadIdx.x;
    const int wid = tid >> 5;
    const int lane = tid & 31;
    const int g  = lane >> 2;
    const int tg = lane & 3;
    const int f4 = tid & 15;
    const int cr = tid >> 4;

    int mk[5], mp[5];
#pragma unroll
    for (int r = 0; r < 5; ++r) {
        int e = tid + 256 * r;
        mk[r] = e >> 6;
        mp[r] = e & 63;
    }

    float acc[3][4];
#pragma unroll
    for (int nt = 0; nt < 3; ++nt)
#pragma unroll
        for (int q = 0; q < 4; ++q) acc[nt][q] = 0.f;

    float cntAcc = 0.f, sqAcc = 0.f;
    const int b = blockIdx.x;
    const int nTiles = BASE_TILES + (b < EXTRA ? 1 : 0);
    const int tile0  = (b < EXTRA) ? b * (BASE_TILES + 1)
                                   : EXTRA * (BASE_TILES + 1) + (b - EXTRA) * BASE_TILES;
    const int rowA0 = 16 * wid + g;
    size_t p0 = (size_t)tile0 * TK;

    // ---- prologue: load tile 0 -------------------------------------------
    float4 av[4], bv[4];
    int mreg[5];
#pragma unroll
    for (int i = 0; i < 4; ++i) {
        int c = cr + 16 * i;
        av[i] = *(const float4*)(v1g + (size_t)c * P + p0 + 4 * f4);
        bv[i] = *(const float4*)(v2g + (size_t)c * P + p0 + 4 * f4);
    }
#pragma unroll
    for (int r = 0; r < 5; ++r)
        mreg[r] = masks[(size_t)mk[r] * P + p0 + mp[r]];

    for (int t = 0; t < nTiles; ++t) {
        const size_t p1 = p0 + TK;
        __syncthreads();   // prev tile's D reads done: s_a, s_bf free

        // ---- Phase A: store v1; squares of v1 and v2; prefetch v1 ---------
        float4 pp1 = make_float4(0.f, 0.f, 0.f, 0.f);
        float4 pp2 = make_float4(0.f, 0.f, 0.f, 0.f);
#pragma unroll
        for (int i = 0; i < 4; ++i) {
            int c = cr + 16 * i;
            float4 a = av[i];
            pp1.x = fmaf(a.x, a.x, pp1.x); pp1.y = fmaf(a.y, a.y, pp1.y);
            pp1.z = fmaf(a.z, a.z, pp1.z); pp1.w = fmaf(a.w, a.w, pp1.w);
            *(float4*)&s_a[c * ASTRIDE + 4 * f4] = a;
            float4 bb = bv[i];
            pp2.x = fmaf(bb.x, bb.x, pp2.x); pp2.y = fmaf(bb.y, bb.y, pp2.y);
            pp2.z = fmaf(bb.z, bb.z, pp2.z); pp2.w = fmaf(bb.w, bb.w, pp2.w);
        }
        *(float4*)&s_red1[tid * 4] = pp1;
        *(float4*)&s_red2[tid * 4] = pp2;

        if (t + 1 < nTiles) {
#pragma unroll
            for (int i = 0; i < 4; ++i)
                av[i] = *(const float4*)(v1g + (size_t)(cr + 16 * i) * P + p1 + 4 * f4);
        }
        __syncthreads();

        // ---- Phase B: reduce per-pixel norms (64 threads) -----------------
        if (tid < TK) {
            int q = tid >> 2, cm = tid & 3;
            float s1 = 0.f, s2 = 0.f;
#pragma unroll
            for (int r = 0; r < 16; ++r) {
                s1 += s_red1[(r * 16 + q) * 4 + cm];
                s2 += s_red2[(r * 16 + q) * 4 + cm];
            }
            s_s1[tid]  = s1;
            s_inv[tid] = 1.0f / fmaxf(sqrtf(s2), EPS);
        }
        __syncthreads();

        // ---- Phase C: v2n straight from registers; B tile; prefetch -------
        {
            float4 iv = *(const float4*)&s_inv[4 * f4];
#pragma unroll
            for (int i = 0; i < 4; ++i) {
                int c = cr + 16 * i;
                float4 bb = bv[i];
                bb.x *= iv.x; bb.y *= iv.y; bb.z *= iv.z; bb.w *= iv.w;
                *(float4*)&s_a[(64 + c) * ASTRIDE + 4 * f4] = bb;
            }
        }
#pragma unroll
        for (int r = 0; r < 5; ++r)
            s_bf[mk[r] * ASTRIDE + mp[r]] = (float)(mreg[r] & 1);
        s_bf[(20 + (tid >> 6)) * ASTRIDE + (tid & 63)] = 0.f;

        if (t + 1 < nTiles) {
#pragma unroll
            for (int i = 0; i < 4; ++i)
                bv[i] = *(const float4*)(v2g + (size_t)(cr + 16 * i) * P + p1 + 4 * f4);
#pragma unroll
            for (int r = 0; r < 5; ++r)
                mreg[r] = masks[(size_t)mk[r] * P + p1 + mp[r]];
        }
        __syncthreads();

        // ---- Phase D: hi-only MMA over 8 k-steps --------------------------
#pragma unroll
        for (int s = 0; s < 8; ++s) {
            int c0 = 8 * s + tg;
            int c1 = c0 + 4;
            uint32_t a0 = to_tf32(s_a[rowA0 * ASTRIDE + c0]);
            uint32_t a1 = to_tf32(s_a[(rowA0 + 8) * ASTRIDE + c0]);
            uint32_t a2 = to_tf32(s_a[rowA0 * ASTRIDE + c1]);
            uint32_t a3 = to_tf32(s_a[(rowA0 + 8) * ASTRIDE + c1]);
#pragma unroll
            for (int nt = 0; nt < 3; ++nt) {
                int n0 = 8 * nt + g;
                uint32_t b0 = __float_as_uint(s_bf[n0 * ASTRIDE + c0]);
                uint32_t b1 = __float_as_uint(s_bf[n0 * ASTRIDE + c1]);
                mma_tf32(acc[nt][0], acc[nt][1], acc[nt][2], acc[nt][3],
                         a0, a1, a2, a3, b0, b1);
            }
        }
        // cnt/sq: 160 threads, 8 per instance, 8-wide shuffle reduce
        if (tid < 8 * K) {
            const int k   = tid >> 3;
            const int sub = tid & 7;
            float c0 = 0.f, s0 = 0.f;
#pragma unroll
            for (int j = 0; j < 8; ++j) {
                int p = sub + 8 * j;
                float m = s_bf[k * ASTRIDE + p];
                c0 += m;
                s0 = fmaf(m, s_s1[p], s0);
            }
#pragma unroll
            for (int off = 1; off < 8; off <<= 1) {
                c0 += __shfl_xor_sync(0xFFFFFFFFu, c0, off);
                s0 += __shfl_xor_sync(0xFFFFFFFFu, s0, off);
            }
            if (sub == 0) { cntAcc += c0; sqAcc += s0; }
        }
        p0 = p1;
    }

    // ---- epilogue: atomics into g_red -------------------------------------
    {
        int m0 = rowA0;
        int m1 = rowA0 + 8;
        int off0 = (m0 < 64) ? (OFF_SUM1 + m0) : (OFF_USUM + (m0 - 64));
        int off1 = (m1 < 64) ? (OFF_SUM1 + m1) : (OFF_USUM + (m1 - 64));
#pragma unroll
        for (int nt = 0; nt < 3; ++nt) {
            int n0 = 8 * nt + 2 * tg;
            if (n0 < K) {
                atomicAdd(&g_red[off0 + n0 * C], acc[nt][0]);
                atomicAdd(&g_red[off1 + n0 * C], acc[nt][2]);
            }
            if (n0 + 1 < K) {
                atomicAdd(&g_red[off0 + (n0 + 1) * C], acc[nt][1]);
                atomicAdd(&g_red[off1 + (n0 + 1) * C], acc[nt][3]);
            }
        }
    }
    if (tid < 8 * K && (tid & 7) == 0) {
        atomicAdd(&g_red[OFF_CNT + (tid >> 3)], cntAcc);
        atomicAdd(&g_red[OFF_SQ  + (tid >> 3)], sqAcc);
    }

    // ---- ticket: last block finalizes -------------------------------------
    __syncthreads();
    if (tid == 0) {
        __threadfence();
        unsigned int tk = atomicAdd(&g_ticket, 1u);
        isLast = (tk == (unsigned int)(GRID - 1)) ? 1u : 0u;
    }
    __syncthreads();
    if (!isLast) return;
    __threadfence();

    // ---- finalize (256 threads; scratch in dead dynamic smem) -------------
    float* S    = dyn;             // [2600]
    float* m1n  = dyn + 2600;      // [K*C]
    float* simm = dyn + 3880;      // [K*K]
    __shared__ float stdv[K];
    __shared__ int   s_cls[K];

    for (int i = tid; i < PART_STRIDE; i += 256) S[i] = g_red[i];
    if (tid < K) s_cls[tid] = labels[tid];
    __syncthreads();

    // reset globals for next graph replay (S holds the values now)
    for (int i = tid; i < PART_STRIDE; i += 256) g_red[i] = 0.f;
    if (tid == 0) g_ticket = 0u;

    // per-instance stats: warp per k, 3 rounds
    for (int k = wid; k < K; k += 8) {
        float cnt = S[OFF_CNT + k];
        float rc  = 1.0f / cnt;
        float v0 = S[OFF_SUM1 + k * C + lane];
        float v1 = S[OFF_SUM1 + k * C + lane + 32];
        float ssum = v0 + v1;
        float m0 = v0 * rc, m1 = v1 * rc;
        float nrm2 = fmaf(m0, m0, m1 * m1);
#pragma unroll
        for (int off = 16; off > 0; off >>= 1) {
            ssum += __shfl_xor_sync(0xFFFFFFFFu, ssum, off);
            nrm2 += __shfl_xor_sync(0xFFFFFFFFu, nrm2, off);
        }
        float n_elem = cnt * (float)C;
        float em  = ssum / n_elem;
        if (lane == 0) {
            float var = (S[OFF_SQ + k] - n_elem * em * em) / (n_elem - 1.0f);
            stdv[k] = sqrtf(fmaxf(var, 0.0f));
        }
        float inv = 1.0f / fmaxf(sqrtf(nrm2), EPS);
        m1n[k * C + lane]      = m0 * inv;
        m1n[k * C + lane + 32] = m1 * inv;
        S[OFF_USUM + k * C + lane]      *= rc;
        S[OFF_USUM + k * C + lane + 32] *= rc;
    }
    __syncthreads();

    // sim dots: 400 over 256 threads, 4-way split accumulators
    for (int e = tid; e < K * K; e += 256) {
        int ki = e / K;
        int kj = e - ki * K;
        const float* a = &m1n[ki * C];
        const float* bb = &S[OFF_USUM + kj * C];
        float d0 = 0.f, d1 = 0.f, d2 = 0.f, d3 = 0.f;
#pragma unroll
        for (int cc = 0; cc < C; cc += 4) {
            d0 = fmaf(a[cc],     bb[cc],     d0);
            d1 = fmaf(a[cc + 1], bb[cc + 1], d1);
            d2 = fmaf(a[cc + 2], bb[cc + 2], d2);
            d3 = fmaf(a[cc + 3], bb[cc + 3], d3);
        }
        simm[e] = (d0 + d1) + (d2 + d3);
    }
    __syncthreads();

    if (wid == 0) {
        float ns = 0.f, nc = 0.f;
        for (int e = lane; e < K * K; e += 32) {
            int ki = e / K, kj = e - ki * K;
            if (s_cls[ki] != s_cls[kj]) { ns += simm[e]; nc += 1.0f; }
        }
#pragma unroll
        for (int off = 16; off > 0; off >>= 1) {
            ns += __shfl_xor_sync(0xFFFFFFFFu, ns, off);
            nc += __shfl_xor_sync(0xFFFFFFFFu, nc, off);
        }
        if (lane == 0) out[22] = ns / nc;
    } else {
        // warps 1-7: classes cl = wid-1, wid+6
        for (int cl = wid - 1; cl < NUM_CLASSES; cl += 7) {
            float inst = 0.f, st = 0.f, cs = 0.f, cnt = 0.f;
            if (lane < K && s_cls[lane] == cl) {
                const int ki = lane;
                inst = simm[ki * K + ki];
                st   = stdv[ki];
                cnt  = 1.0f;
#pragma unroll
                for (int kj = 0; kj < K; ++kj)
                    if (kj != ki && s_cls[kj] == cl) cs += simm[ki * K + kj];
            }
#pragma unroll
            for (int off = 16; off > 0; off >>= 1) {
                inst += __shfl_xor_sync(0xFFFFFFFFu, inst, off);
                st   += __shfl_xor_sync(0xFFFFFFFFu, st,   off);
                cs   += __shfl_xor_sync(0xFFFFFFFFu, cs,   off);
                cnt  += __shfl_xor_sync(0xFFFFFFFFu, cnt,  off);
            }
            if (lane == 0) {
                if (cnt > 1.0f) {
                    inst /= cnt;
                    cs   /= cnt * (cnt - 1.0f);
                    st   /= cnt;
                }
                out[cl]      = inst;
                out[11 + cl] = cs;
                out[23 + cl] = st;
            }
        }
    }
}

extern "C" void kernel_launch(void* const* d_in, const int* in_sizes, int n_in,
                              void* d_out, int out_size)
{
    const float* v1     = (const float*)d_in[0];
    const float* v2     = (const float*)d_in[1];
    const int*   labels = (const int*)d_in[2];
    const int*   masks  = (const int*)d_in[3];
    float* out = (float*)d_out;

    fused_kernel<<<GRID, 256, DYN_SZ>>>(v1, v2, masks, labels, out);
}